// round 12
// baseline (speedup 1.0000x reference)
#include <cuda_runtime.h>
#include <cuda_bf16.h>
#include <cstdint>

// kmeans assignment: persistent-CTA mma.sync bf16 3-term split + exact-chain
// rescue; output bit-identical to the R6 scalar chain (rel_err 9.9065e-4).
// R12: A fragments converted in registers inside the mma loop (no A smem
// roundtrip, no convert sync); screening scores drop the row-constant x2
// (argmin-equivalent; exact chain only in rescue); fused epilogue; uint2 B.

#define DD      50
#define CC_TC   256
#define TILE_M  128
#define MARGIN  0.02f
#define FLT_BIG 3.402823466e38f
#define MAXD    128
#define NSM     152
#define TPBT    512

typedef unsigned long long u64;

// smem byte offsets (dynamic)
#define SM_X0   0
#define SM_X1   (SM_X0 + TILE_M * DD * 4)            // 25600
#define SM_P2   (SM_X1 + TILE_M * DD * 4)            // 51200
#define SM_CNT  (SM_P2 + CC_TC * 4)                  // 52224
#define SM_LST  (SM_CNT + TILE_M * 4)                // 52736
#define SM_PMIN (SM_LST + TILE_M * 8 * 4)            // 56832
#define SM_BF   (SM_PMIN + TILE_M * 2 * 4)           // 57856
#define SM_TOT  (SM_BF + 8 * CC_TC * 4 * 8)          // 123392

// B fragments in mma order: gBfrag[slot<8][c<256][jj<4] = (b0,b1)
// slots 0..3 = Bh ks 0..3, slots 4..7 = Bl ks 0..3
__device__ __align__(16) u64 gBfrag[8 * CC_TC * 4];
__device__ float gP2[CC_TC];

__global__ void prep_kernel(const float* __restrict__ Phi)
{
    const int c = threadIdx.x;                 // 256 threads == 256 centroids
    unsigned short h[64], l[64];
    float s = 0.f;
    for (int d = 0; d < 64; ++d) {
        if (d < DD) {
            const float v  = Phi[c * DD + d];
            const __nv_bfloat16 bh = __float2bfloat16(v);
            const __nv_bfloat16 bl = __float2bfloat16(v - __bfloat162float(bh));
            h[d] = __bfloat16_as_ushort(bh);
            l[d] = __bfloat16_as_ushort(bl);
            s = __fadd_rn(s, __fmul_rn(v, v));  // exact R6 chain
        } else { h[d] = 0; l[d] = 0; }
    }
    gP2[c] = s;
    for (int ks = 0; ks < 4; ++ks)
        for (int jj = 0; jj < 4; ++jj) {
            const int k0 = 16 * ks + 2 * jj;        // b0 elements
            const int k1 = 16 * ks + 8 + 2 * jj;    // b1 elements
            const u64 vh = (u64)((uint32_t)h[k0] | ((uint32_t)h[k0+1] << 16))
                         | ((u64)((uint32_t)h[k1] | ((uint32_t)h[k1+1] << 16)) << 32);
            const u64 vl = (u64)((uint32_t)l[k0] | ((uint32_t)l[k0+1] << 16))
                         | ((u64)((uint32_t)l[k1] | ((uint32_t)l[k1+1] << 16)) << 32);
            gBfrag[(ks * CC_TC + c) * 4 + jj]       = vh;
            gBfrag[((4 + ks) * CC_TC + c) * 4 + jj] = vl;
        }
}

__device__ __forceinline__ uint32_t smem_u32(const void* p) {
    uint32_t a;
    asm("{ .reg .u64 t; cvta.to.shared.u64 t, %1; cvt.u32.u64 %0, t; }"
        : "=r"(a) : "l"(p));
    return a;
}
__device__ __forceinline__ void cp16(uint32_t saddr, const void* g) {
    asm volatile("cp.async.ca.shared.global [%0], [%1], 16;"
                 :: "r"(saddr), "l"(g));
}
__device__ __forceinline__ void mma16816(float* d, uint32_t a0, uint32_t a1,
                                         uint32_t a2, uint32_t a3,
                                         uint32_t b0, uint32_t b1) {
    asm volatile(
        "mma.sync.aligned.m16n8k16.row.col.f32.bf16.bf16.f32 "
        "{%0,%1,%2,%3}, {%4,%5,%6,%7}, {%8,%9}, {%0,%1,%2,%3};"
        : "+f"(d[0]), "+f"(d[1]), "+f"(d[2]), "+f"(d[3])
        : "r"(a0), "r"(a1), "r"(a2), "r"(a3), "r"(b0), "r"(b1));
}
// pack (v.x -> lo16, v.y -> hi16) as bf16x2, round-nearest
__device__ __forceinline__ uint32_t bfpack_hi(float x, float y) {
    uint32_t r;
    asm("cvt.rn.bf16x2.f32 %0, %1, %2;" : "=r"(r) : "f"(y), "f"(x));
    return r;
}
__device__ __forceinline__ uint32_t bfpack_lo(float x, float y) {
    const float hx = __bfloat162float(__float2bfloat16(x));
    const float hy = __bfloat162float(__float2bfloat16(y));
    return bfpack_hi(x - hx, y - hy);
}

__global__ __launch_bounds__(TPBT, 1)
void kmeans_tc(const float* __restrict__ X,
               const float* __restrict__ Phi,
               float* __restrict__ out, int n, int ntiles)
{
    extern __shared__ char smem[];
    const int tid  = threadIdx.x;
    const int w    = tid >> 5;
    const int lane = tid & 31;
    const int rl   = lane >> 2;
    const int jj   = lane & 3;
    const int half = w & 1;              // which 128 centroids
    const int arow = (w >> 1) * 16 + rl; // A row stripe (16 rows/warp-pair)

    float*       sP2 = reinterpret_cast<float*>(smem + SM_P2);
    int*         sCn = reinterpret_cast<int*>(smem + SM_CNT);
    int*         sLs = reinterpret_cast<int*>(smem + SM_LST);
    float*       sPm = reinterpret_cast<float*>(smem + SM_PMIN); // [row][half]
    const uint2* Bf2 = reinterpret_cast<const uint2*>(smem + SM_BF);
    u64*         Bf  = reinterpret_cast<u64*>(smem + SM_BF);

    const uint32_t sx0 = smem_u32(smem + SM_X0);
    const uint32_t sx1 = smem_u32(smem + SM_X1);

    int  tile = blockIdx.x;
    int  buf  = 0;
    bool pref = false;

    // prefetch first tile ASAP
    if (tile < ntiles) {
        const long long base = (long long)tile * TILE_M;
        if (base + TILE_M <= n) {
            const char* src = reinterpret_cast<const char*>(X + base * DD);
            for (int i = tid; i < TILE_M * DD * 4 / 16; i += TPBT)
                cp16(sx0 + i * 16, src + i * 16);
            pref = true;
        }
    }
    asm volatile("cp.async.commit_group;" ::: "memory");

    // one-time per CTA: copy B fragments + p2
    {
        const u64* g = gBfrag;
        for (int i = tid; i < 8 * CC_TC * 4; i += TPBT) Bf[i] = g[i];
        for (int i = tid; i < CC_TC; i += TPBT) sP2[i] = gP2[i];
    }

    for (; tile < ntiles; tile += gridDim.x) {
        const long long gbase = (long long)tile * TILE_M;
        const bool full = (gbase + TILE_M <= n);

        if (pref) asm volatile("cp.async.wait_group 0;" ::: "memory");
        __syncthreads();   // publish current X buffer; prev resolve done

        float* sXf = reinterpret_cast<float*>(smem + (buf ? SM_X1 : SM_X0));
        if (!full) {       // tail tile: direct clamped load
            for (int idx = tid; idx < TILE_M * DD; idx += TPBT) {
                const int r = idx / DD, d = idx - r * DD;
                long long pt = gbase + r; if (pt >= n) pt = n - 1;
                sXf[idx] = X[pt * DD + d];
            }
            __syncthreads();
        }

        // zero candidate counters (owners), then prefetch next tile
        if (half == 0 && jj == 0) { sCn[arow] = 0; sCn[arow + 8] = 0; }
        {
            const int nt = tile + gridDim.x;
            pref = false;
            if (nt < ntiles) {
                const long long nb = (long long)nt * TILE_M;
                if (nb + TILE_M <= n) {
                    const char* src = reinterpret_cast<const char*>(X + nb * DD);
                    const uint32_t dst = buf ? sx0 : sx1;
                    for (int i = tid; i < TILE_M * DD * 4 / 16; i += TPBT)
                        cp16(dst + i * 16, src + i * 16);
                    pref = true;
                }
            }
            asm volatile("cp.async.commit_group;" ::: "memory");
        }

        // ---- mma: A fragments converted in registers per ks-step
        float acc[64];
        #pragma unroll
        for (int i = 0; i < 64; ++i) acc[i] = 0.f;

        const float* xr0 = sXf + arow * DD;
        const float* xr1 = sXf + (arow + 8) * DD;
        const float2 z2 = make_float2(0.f, 0.f);

        // hi-A pass: slots Ah*Bh (ks 0..3) and Ah*Bl (ks 0..3)
        #pragma unroll
        for (int ks = 0; ks < 4; ++ks) {
            const int k0 = 16 * ks + 2 * jj;
            const int k1 = k0 + 8;
            const bool p0ok = (ks < 3) || (jj == 0);
            const bool p1ok = (ks < 3);
            const float2 v00 = p0ok ? *reinterpret_cast<const float2*>(xr0 + k0) : z2;
            const float2 v01 = p0ok ? *reinterpret_cast<const float2*>(xr1 + k0) : z2;
            const float2 v10 = p1ok ? *reinterpret_cast<const float2*>(xr0 + k1) : z2;
            const float2 v11 = p1ok ? *reinterpret_cast<const float2*>(xr1 + k1) : z2;
            const uint32_t a0 = bfpack_hi(v00.x, v00.y);
            const uint32_t a1 = bfpack_hi(v01.x, v01.y);
            const uint32_t a2 = bfpack_hi(v10.x, v10.y);
            const uint32_t a3 = bfpack_hi(v11.x, v11.y);
            const uint2* Bph = Bf2 + ((u64)(ks * CC_TC + half * 128 + rl) * 4 + jj);
            const uint2* Bpl = Bf2 + ((u64)((4 + ks) * CC_TC + half * 128 + rl) * 4 + jj);
            #pragma unroll
            for (int t = 0; t < 16; ++t) {
                const uint2 b = Bph[t * 32];
                mma16816(acc + t * 4, a0, a1, a2, a3, b.x, b.y);
            }
            #pragma unroll
            for (int t = 0; t < 16; ++t) {
                const uint2 b = Bpl[t * 32];
                mma16816(acc + t * 4, a0, a1, a2, a3, b.x, b.y);
            }
        }
        // lo-A pass: slots Al*Bh (ks 0..3)
        #pragma unroll
        for (int ks = 0; ks < 4; ++ks) {
            const int k0 = 16 * ks + 2 * jj;
            const int k1 = k0 + 8;
            const bool p0ok = (ks < 3) || (jj == 0);
            const bool p1ok = (ks < 3);
            const float2 v00 = p0ok ? *reinterpret_cast<const float2*>(xr0 + k0) : z2;
            const float2 v01 = p0ok ? *reinterpret_cast<const float2*>(xr1 + k0) : z2;
            const float2 v10 = p1ok ? *reinterpret_cast<const float2*>(xr0 + k1) : z2;
            const float2 v11 = p1ok ? *reinterpret_cast<const float2*>(xr1 + k1) : z2;
            const uint32_t a0 = bfpack_lo(v00.x, v00.y);
            const uint32_t a1 = bfpack_lo(v01.x, v01.y);
            const uint32_t a2 = bfpack_lo(v10.x, v10.y);
            const uint32_t a3 = bfpack_lo(v11.x, v11.y);
            const uint2* Bph = Bf2 + ((u64)(ks * CC_TC + half * 128 + rl) * 4 + jj);
            #pragma unroll
            for (int t = 0; t < 16; ++t) {
                const uint2 b = Bph[t * 32];
                mma16816(acc + t * 4, a0, a1, a2, a3, b.x, b.y);
            }
        }

        // ---- epilogue: screening score t = p2 - 2*mm (x2 dropped: row-
        // constant, argmin-equivalent; exact chain lives in the rescue)
        const int row0 = arow;
        const int row1 = arow + 8;

        float mn0 = FLT_BIG, mn1 = FLT_BIG;
        #pragma unroll
        for (int t = 0; t < 16; ++t) {
            const int c0 = half * 128 + t * 8 + 2 * jj;
            const float p0 = sP2[c0], p1 = sP2[c0 + 1];
            const float s00 = __fmaf_rn(-2.f, acc[t*4+0], p0);
            const float s01 = __fmaf_rn(-2.f, acc[t*4+1], p1);
            const float s10 = __fmaf_rn(-2.f, acc[t*4+2], p0);
            const float s11 = __fmaf_rn(-2.f, acc[t*4+3], p1);
            acc[t*4+0] = s00; acc[t*4+1] = s01;
            acc[t*4+2] = s10; acc[t*4+3] = s11;
            mn0 = fminf(mn0, fminf(s00, s01));
            mn1 = fminf(mn1, fminf(s10, s11));
        }
        mn0 = fminf(mn0, __shfl_xor_sync(0xFFFFFFFF, mn0, 1));
        mn0 = fminf(mn0, __shfl_xor_sync(0xFFFFFFFF, mn0, 2));
        mn1 = fminf(mn1, __shfl_xor_sync(0xFFFFFFFF, mn1, 1));
        mn1 = fminf(mn1, __shfl_xor_sync(0xFFFFFFFF, mn1, 2));
        if (jj == 0) {
            sPm[row0 * 2 + half] = mn0;
            sPm[row1 * 2 + half] = mn1;
        }
        __syncthreads();
        const float thr0 = fminf(sPm[row0 * 2], sPm[row0 * 2 + 1]) + MARGIN;
        const float thr1 = fminf(sPm[row1 * 2], sPm[row1 * 2 + 1]) + MARGIN;

        #pragma unroll
        for (int t = 0; t < 16; ++t) {
            const int c0 = half * 128 + t * 8 + 2 * jj;
            if (acc[t*4+0] < thr0) { int p = atomicAdd(&sCn[row0], 1); if (p < 8) sLs[row0*8+p] = c0;     }
            if (acc[t*4+1] < thr0) { int p = atomicAdd(&sCn[row0], 1); if (p < 8) sLs[row0*8+p] = c0 + 1; }
            if (acc[t*4+2] < thr1) { int p = atomicAdd(&sCn[row1], 1); if (p < 8) sLs[row1*8+p] = c0;     }
            if (acc[t*4+3] < thr1) { int p = atomicAdd(&sCn[row1], 1); if (p < 8) sLs[row1*8+p] = c0 + 1; }
        }
        __syncthreads();

        // resolve: even warp of each pair, lanes jj==0 own 2 rows each
        if (half == 0 && jj == 0) {
            #pragma unroll
            for (int rr = 0; rr < 2; ++rr) {
                const int row = rr ? row1 : row0;
                const int cnt = sCn[row];
                int pick;
                if (cnt == 1) {
                    pick = sLs[row * 8];     // provably the exact-chain argmin
                } else {
                    // exact R6 chain: x2 then per-candidate score
                    const float* xr = sXf + row * DD;
                    float x2 = 0.f;
                    #pragma unroll
                    for (int d = 0; d < DD; ++d)
                        x2 = __fadd_rn(x2, __fmul_rn(xr[d], xr[d]));
                    float bs = FLT_BIG; int bc = CC_TC; pick = 0;
                    if (cnt <= 8) {
                        for (int i = 0; i < cnt; ++i) {
                            const int c = sLs[row * 8 + i];
                            float mm = 0.f;
                            #pragma unroll
                            for (int d = 0; d < DD; ++d)
                                mm = __fmaf_rn(xr[d], __ldg(&Phi[c * DD + d]), mm);
                            const float s = __fsub_rn(__fadd_rn(x2, sP2[c]),
                                                      __fmul_rn(2.f, mm));
                            if (s < bs || (s == bs && c < bc)) { bs = s; bc = c; }
                        }
                        pick = bc;
                    } else {                 // truncated list: full exact scan
                        for (int c = 0; c < CC_TC; ++c) {
                            float mm = 0.f;
                            #pragma unroll
                            for (int d = 0; d < DD; ++d)
                                mm = __fmaf_rn(xr[d], __ldg(&Phi[c * DD + d]), mm);
                            const float s = __fsub_rn(__fadd_rn(x2, sP2[c]),
                                                      __fmul_rn(2.f, mm));
                            if (s < bs) { bs = s; pick = c; }
                        }
                    }
                }
                if (gbase + row < n) out[gbase + row] = (float)pick;
            }
        }
        buf ^= 1;
    }
}

// --------------------- R6 scalar fallback (D==50, any C) ---------------------
#define TPB   384
#define CHUNK 128
#define PPT   2
#define PTS_PER_BLOCK (TPB * PPT)

__global__ __launch_bounds__(TPB)
void kmeans_fast50(const float* __restrict__ X,
                   const float* __restrict__ Phi,
                   float* __restrict__ out, int n, int C)
{
    __shared__ __align__(16) float sPhiT[DD * CHUNK];
    __shared__ float sP2[CHUNK];

    const int base = blockIdx.x * PTS_PER_BLOCK;
    const int pt0  = base + threadIdx.x;
    const int pt1  = pt0 + TPB;

    float x0[DD], x1[DD];
    {
        const long long r0 = (long long)(pt0 < n ? pt0 : 0) * DD;
        const long long r1 = (long long)(pt1 < n ? pt1 : 0) * DD;
        const float2* a = reinterpret_cast<const float2*>(X + r0);
        const float2* b = reinterpret_cast<const float2*>(X + r1);
        #pragma unroll
        for (int j = 0; j < DD / 2; ++j) {
            float2 va = a[j]; x0[2*j] = va.x; x0[2*j+1] = va.y;
            float2 vb = b[j]; x1[2*j] = vb.x; x1[2*j+1] = vb.y;
        }
    }
    float x2a = 0.f, x2b = 0.f;
    #pragma unroll
    for (int d = 0; d < DD; ++d) {
        x2a = __fadd_rn(x2a, __fmul_rn(x0[d], x0[d]));
        x2b = __fadd_rn(x2b, __fmul_rn(x1[d], x1[d]));
    }

    float best0 = FLT_BIG, best1 = FLT_BIG;
    int   bi0 = 0, bi1 = 0;

    #pragma unroll 1
    for (int cb = 0; cb < C; cb += CHUNK) {
        const int cc = (C - cb < CHUNK) ? (C - cb) : CHUNK;
        __syncthreads();
        for (int i = threadIdx.x; i < cc * DD; i += TPB) {
            const int c = i / DD, d = i - c * DD;
            sPhiT[d * CHUNK + c] = Phi[(long long)(cb + c) * DD + d];
        }
        __syncthreads();
        if (threadIdx.x < cc) {
            float s = 0.f;
            #pragma unroll
            for (int d = 0; d < DD; ++d) {
                const float v = sPhiT[d * CHUNK + threadIdx.x];
                s = __fadd_rn(s, __fmul_rn(v, v));
            }
            sP2[threadIdx.x] = s;
        }
        __syncthreads();

        int c = 0;
        #pragma unroll 1
        for (; c + 4 <= cc; c += 4) {
            float a00=0.f,a01=0.f,a02=0.f,a03=0.f,a10=0.f,a11=0.f,a12=0.f,a13=0.f;
            const float4* pT = reinterpret_cast<const float4*>(sPhiT + c);
            #pragma unroll
            for (int d = 0; d < DD; ++d) {
                const float4 p = pT[d * (CHUNK / 4)];
                a00 = __fmaf_rn(x0[d], p.x, a00);
                a01 = __fmaf_rn(x0[d], p.y, a01);
                a02 = __fmaf_rn(x0[d], p.z, a02);
                a03 = __fmaf_rn(x0[d], p.w, a03);
                a10 = __fmaf_rn(x1[d], p.x, a10);
                a11 = __fmaf_rn(x1[d], p.y, a11);
                a12 = __fmaf_rn(x1[d], p.z, a12);
                a13 = __fmaf_rn(x1[d], p.w, a13);
            }
            const float q0=sP2[c],q1=sP2[c+1],q2=sP2[c+2],q3=sP2[c+3];
            const float s00=__fsub_rn(__fadd_rn(x2a,q0),__fmul_rn(2.f,a00));
            const float s01=__fsub_rn(__fadd_rn(x2a,q1),__fmul_rn(2.f,a01));
            const float s02=__fsub_rn(__fadd_rn(x2a,q2),__fmul_rn(2.f,a02));
            const float s03=__fsub_rn(__fadd_rn(x2a,q3),__fmul_rn(2.f,a03));
            const float s10=__fsub_rn(__fadd_rn(x2b,q0),__fmul_rn(2.f,a10));
            const float s11=__fsub_rn(__fadd_rn(x2b,q1),__fmul_rn(2.f,a11));
            const float s12=__fsub_rn(__fadd_rn(x2b,q2),__fmul_rn(2.f,a12));
            const float s13=__fsub_rn(__fadd_rn(x2b,q3),__fmul_rn(2.f,a13));
            const int g = cb + c;
            if (s00<best0){best0=s00;bi0=g;}   if (s01<best0){best0=s01;bi0=g+1;}
            if (s02<best0){best0=s02;bi0=g+2;} if (s03<best0){best0=s03;bi0=g+3;}
            if (s10<best1){best1=s10;bi1=g;}   if (s11<best1){best1=s11;bi1=g+1;}
            if (s12<best1){best1=s12;bi1=g+2;} if (s13<best1){best1=s13;bi1=g+3;}
        }
        for (; c < cc; ++c) {
            float a0=0.f,a1=0.f;
            #pragma unroll
            for (int d = 0; d < DD; ++d) {
                const float p = sPhiT[d * CHUNK + c];
                a0=__fmaf_rn(x0[d],p,a0); a1=__fmaf_rn(x1[d],p,a1);
            }
            const float q = sP2[c];
            const float s0=__fsub_rn(__fadd_rn(x2a,q),__fmul_rn(2.f,a0));
            const float s1=__fsub_rn(__fadd_rn(x2b,q),__fmul_rn(2.f,a1));
            if (s0<best0){best0=s0;bi0=cb+c;}
            if (s1<best1){best1=s1;bi1=cb+c;}
        }
    }
    if (pt0 < n) out[pt0] = (float)bi0;
    if (pt1 < n) out[pt1] = (float)bi1;
}

// --------------------- generic fallback: any D, C ---------------------
__global__ __launch_bounds__(256)
void kmeans_generic(const float* __restrict__ X,
                    const float* __restrict__ Phi,
                    float* __restrict__ out, int n, int D, int C)
{
    for (int idx = blockIdx.x * blockDim.x + threadIdx.x; idx < n;
         idx += gridDim.x * blockDim.x) {
        float xr[MAXD];
        const int Dc = (D < MAXD) ? D : MAXD;
        const long long row = (long long)idx * D;
        for (int d = 0; d < Dc; ++d) xr[d] = X[row + d];
        float x2 = 0.f;
        for (int d = 0; d < Dc; ++d) x2 = __fadd_rn(x2, __fmul_rn(xr[d], xr[d]));
        float best = FLT_BIG; int bi = 0;
        for (int c = 0; c < C; ++c) {
            const long long pr = (long long)c * D;
            float mm = 0.f, p2 = 0.f;
            for (int d = 0; d < Dc; ++d) {
                const float pv = __ldg(&Phi[pr + d]);
                mm = __fmaf_rn(xr[d], pv, mm);
                p2 = __fadd_rn(p2, __fmul_rn(pv, pv));
            }
            const float s = __fsub_rn(__fadd_rn(x2, p2), __fmul_rn(2.f, mm));
            if (s < best) { best = s; bi = c; }
        }
        out[idx] = (float)bi;
    }
}

// ------------------------------ launch ------------------------------
extern "C" void kernel_launch(void* const* d_in, const int* in_sizes, int n_in,
                              void* d_out, int out_size)
{
    int iX = 0;
    for (int i = 1; i < n_in; ++i)
        if (in_sizes[i] > in_sizes[iX]) iX = i;
    int iP = (iX == 0) ? (n_in > 1 ? 1 : 0) : 0;
    for (int i = 0; i < n_in; ++i)
        if (i != iX && in_sizes[i] > in_sizes[iP]) iP = i;

    const float* X   = (const float*)d_in[iX];
    const float* Phi = (const float*)d_in[iP];
    float*       out = (float*)d_out;

    const int n = out_size;
    if (n <= 0) return;
    const int D = in_sizes[iX] / n;
    const int C = (D > 0) ? in_sizes[iP] / D : 0;
    if (D <= 0 || C <= 0) return;

    if (D == DD && C == CC_TC) {
        prep_kernel<<<1, 256>>>(Phi);
        cudaFuncSetAttribute(kmeans_tc,
                             cudaFuncAttributeMaxDynamicSharedMemorySize, SM_TOT);
        const int ntiles = (n + TILE_M - 1) / TILE_M;
        const int grid = (ntiles < NSM) ? ntiles : NSM;
        kmeans_tc<<<grid, TPBT, SM_TOT>>>(X, Phi, out, n, ntiles);
    } else if (D == DD) {
        const int blocks = (n + PTS_PER_BLOCK - 1) / PTS_PER_BLOCK;
        kmeans_fast50<<<blocks, TPB>>>(X, Phi, out, n, C);
    } else {
        int blocks = (n + 255) / 256;
        if (blocks > 65535 * 8) blocks = 65535 * 8;
        kmeans_generic<<<blocks, 256>>>(X, Phi, out, n, D, C);
    }
}

// round 13
// speedup vs baseline: 1.0837x; 1.0837x over previous
#include <cuda_runtime.h>
#include <cuda_bf16.h>
#include <cstdint>

// kmeans assignment: persistent-CTA mma.sync bf16 3-term split + exact-chain
// rescue; output bit-identical to the R6 scalar chain (rel_err 9.9065e-4).
// R13: each warp covers 32 A-rows (2 stripes) x 64 centroids -> every B
// fragment load feeds TWO mma (B smem traffic halved; L1 was the binding
// pipe at 56.6%). Screening drops row-constant x2 (validated in R12);
// exact chain lives in the rescue. A fragments staged in smem (R11 path,
// no register-pressure spills).

#define DD      50
#define CC_TC   256
#define TILE_M  128
#define MARGIN  0.02f
#define FLT_BIG 3.402823466e38f
#define MAXD    128
#define NSM     152
#define TPBT    512

typedef unsigned long long u64;

// smem byte offsets (dynamic)
#define SM_X0   0
#define SM_X1   (SM_X0 + TILE_M * DD * 4)            // 25600
#define SM_P2   (SM_X1 + TILE_M * DD * 4)            // 51200
#define SM_CNT  (SM_P2 + CC_TC * 4)                  // 52224
#define SM_LST  (SM_CNT + TILE_M * 4)                // 52736
#define SM_PMIN (SM_LST + TILE_M * 8 * 4)            // 56832
#define SM_AH   (SM_PMIN + TILE_M * 4 * 4)           // 58880
#define SM_AL   (SM_AH + 4 * TILE_M * 4 * 8)         // 75264
#define SM_BF   (SM_AL + 4 * TILE_M * 4 * 8)         // 91648
#define SM_TOT  (SM_BF + 8 * CC_TC * 4 * 8)          // 157184

// B fragments in mma order: gBfrag[slot<8][c<256][jj<4] = (b0,b1)
// slots 0..3 = Bh ks 0..3, slots 4..7 = Bl ks 0..3
__device__ __align__(16) u64 gBfrag[8 * CC_TC * 4];
__device__ float gP2[CC_TC];

__global__ void prep_kernel(const float* __restrict__ Phi)
{
    const int c = threadIdx.x;                 // 256 threads == 256 centroids
    unsigned short h[64], l[64];
    float s = 0.f;
    for (int d = 0; d < 64; ++d) {
        if (d < DD) {
            const float v  = Phi[c * DD + d];
            const __nv_bfloat16 bh = __float2bfloat16(v);
            const __nv_bfloat16 bl = __float2bfloat16(v - __bfloat162float(bh));
            h[d] = __bfloat16_as_ushort(bh);
            l[d] = __bfloat16_as_ushort(bl);
            s = __fadd_rn(s, __fmul_rn(v, v));  // exact R6 chain
        } else { h[d] = 0; l[d] = 0; }
    }
    gP2[c] = s;
    for (int ks = 0; ks < 4; ++ks)
        for (int jj = 0; jj < 4; ++jj) {
            const int k0 = 16 * ks + 2 * jj;        // b0 elements
            const int k1 = 16 * ks + 8 + 2 * jj;    // b1 elements
            const u64 vh = (u64)((uint32_t)h[k0] | ((uint32_t)h[k0+1] << 16))
                         | ((u64)((uint32_t)h[k1] | ((uint32_t)h[k1+1] << 16)) << 32);
            const u64 vl = (u64)((uint32_t)l[k0] | ((uint32_t)l[k0+1] << 16))
                         | ((u64)((uint32_t)l[k1] | ((uint32_t)l[k1+1] << 16)) << 32);
            gBfrag[(ks * CC_TC + c) * 4 + jj]       = vh;
            gBfrag[((4 + ks) * CC_TC + c) * 4 + jj] = vl;
        }
}

__device__ __forceinline__ uint32_t smem_u32(const void* p) {
    uint32_t a;
    asm("{ .reg .u64 t; cvta.to.shared.u64 t, %1; cvt.u32.u64 %0, t; }"
        : "=r"(a) : "l"(p));
    return a;
}
__device__ __forceinline__ void cp16(uint32_t saddr, const void* g) {
    asm volatile("cp.async.ca.shared.global [%0], [%1], 16;"
                 :: "r"(saddr), "l"(g));
}
__device__ __forceinline__ void mma16816(float* d, uint32_t a0, uint32_t a1,
                                         uint32_t a2, uint32_t a3,
                                         uint32_t b0, uint32_t b1) {
    asm volatile(
        "mma.sync.aligned.m16n8k16.row.col.f32.bf16.bf16.f32 "
        "{%0,%1,%2,%3}, {%4,%5,%6,%7}, {%8,%9}, {%0,%1,%2,%3};"
        : "+f"(d[0]), "+f"(d[1]), "+f"(d[2]), "+f"(d[3])
        : "r"(a0), "r"(a1), "r"(a2), "r"(a3), "r"(b0), "r"(b1));
}

__global__ __launch_bounds__(TPBT, 1)
void kmeans_tc(const float* __restrict__ X,
               const float* __restrict__ Phi,
               float* __restrict__ out, int n, int ntiles)
{
    extern __shared__ char smem[];
    const int tid  = threadIdx.x;
    const int w    = tid >> 5;
    const int lane = tid & 31;
    const int rl   = lane >> 2;
    const int jj   = lane & 3;
    const int q    = w & 3;              // centroid quarter (64 centroids)
    const int g    = w >> 2;             // row group (32 rows)
    const int cbase = q * 64;
    const int rA0 = g * 32 + rl;         // stripe0 rows: rA0, rA0+8
    const int rB0 = g * 32 + 16 + rl;    // stripe1 rows: rB0, rB0+8

    float*       sP2 = reinterpret_cast<float*>(smem + SM_P2);
    int*         sCn = reinterpret_cast<int*>(smem + SM_CNT);
    int*         sLs = reinterpret_cast<int*>(smem + SM_LST);
    float*       sPm = reinterpret_cast<float*>(smem + SM_PMIN); // [row][q]
    uint32_t*    AhW = reinterpret_cast<uint32_t*>(smem + SM_AH);
    uint32_t*    AlW = reinterpret_cast<uint32_t*>(smem + SM_AL);
    const uint2* Ah2 = reinterpret_cast<const uint2*>(smem + SM_AH);
    const uint2* Al2 = reinterpret_cast<const uint2*>(smem + SM_AL);
    const uint2* Bf2 = reinterpret_cast<const uint2*>(smem + SM_BF);
    u64*         Bf  = reinterpret_cast<u64*>(smem + SM_BF);

    const uint32_t sx0 = smem_u32(smem + SM_X0);
    const uint32_t sx1 = smem_u32(smem + SM_X1);

    int  tile = blockIdx.x;
    int  buf  = 0;
    bool pref = false;

    // prefetch first tile ASAP
    if (tile < ntiles) {
        const long long base = (long long)tile * TILE_M;
        if (base + TILE_M <= n) {
            const char* src = reinterpret_cast<const char*>(X + base * DD);
            for (int i = tid; i < TILE_M * DD * 4 / 16; i += TPBT)
                cp16(sx0 + i * 16, src + i * 16);
            pref = true;
        }
    }
    asm volatile("cp.async.commit_group;" ::: "memory");

    // one-time per CTA: copy B fragments + p2, zero A pad words (ks=3,q=1..7)
    {
        const u64* gb = gBfrag;
        for (int i = tid; i < 8 * CC_TC * 4; i += TPBT) Bf[i] = gb[i];
        for (int i = tid; i < CC_TC; i += TPBT) sP2[i] = gP2[i];
        for (int i = tid; i < TILE_M * 7 * 2; i += TPBT) {
            const int a = i / (TILE_M * 7);
            const int j = i - a * (TILE_M * 7);
            const int r = j / 7, qq = 1 + (j - r * 7);
            const int u = 3 * 1024 + r * 8 + (qq & 3) * 2 + (qq >> 2);
            (a ? AlW : AhW)[u] = 0u;
        }
    }

    for (; tile < ntiles; tile += gridDim.x) {
        const long long gbase = (long long)tile * TILE_M;
        const bool full = (gbase + TILE_M <= n);

        if (pref) asm volatile("cp.async.wait_group 0;" ::: "memory");
        __syncthreads();   // publish current X buffer; prev resolve done

        float* sXf = reinterpret_cast<float*>(smem + (buf ? SM_X1 : SM_X0));
        if (!full) {
            for (int idx = tid; idx < TILE_M * DD; idx += TPBT) {
                const int r = idx / DD, d = idx - r * DD;
                long long pt = gbase + r; if (pt >= n) pt = n - 1;
                sXf[idx] = X[pt * DD + d];
            }
            __syncthreads();
        }

        // owners zero candidate counters for their 4 rows
        if (q == 0 && jj == 0) {
            sCn[rA0] = 0; sCn[rA0 + 8] = 0;
            sCn[rB0] = 0; sCn[rB0 + 8] = 0;
        }

        // convert X -> bf16 hi/lo, fragment-ordered u32 slots (R11 layout)
        for (int idx = tid; idx < TILE_M * 25; idx += TPBT) {
            const int r = idx / 25, p = idx - r * 25;
            const float2 v = *reinterpret_cast<const float2*>(sXf + r * DD + 2 * p);
            const __nv_bfloat16 h0 = __float2bfloat16(v.x);
            const __nv_bfloat16 h1 = __float2bfloat16(v.y);
            const __nv_bfloat16 l0 = __float2bfloat16(v.x - __bfloat162float(h0));
            const __nv_bfloat16 l1 = __float2bfloat16(v.y - __bfloat162float(h1));
            const int ks = p >> 3, qq = p & 7;
            const int u  = ks * 1024 + r * 8 + (qq & 3) * 2 + (qq >> 2);
            AhW[u] = (uint32_t)__bfloat16_as_ushort(h0)
                   | ((uint32_t)__bfloat16_as_ushort(h1) << 16);
            AlW[u] = (uint32_t)__bfloat16_as_ushort(l0)
                   | ((uint32_t)__bfloat16_as_ushort(l1) << 16);
        }
        __syncthreads();

        // prefetch next tile (overlaps mma + epilogue)
        {
            const int nt = tile + gridDim.x;
            pref = false;
            if (nt < ntiles) {
                const long long nb = (long long)nt * TILE_M;
                if (nb + TILE_M <= n) {
                    const char* src = reinterpret_cast<const char*>(X + nb * DD);
                    const uint32_t dst = buf ? sx0 : sx1;
                    for (int i = tid; i < TILE_M * DD * 4 / 16; i += TPBT)
                        cp16(dst + i * 16, src + i * 16);
                    pref = true;
                }
            }
            asm volatile("cp.async.commit_group;" ::: "memory");
        }

        // ---- mma: 12 slots; per slot load 4 A frags (2 stripes), then
        // each B fragment load feeds 2 mma (B smem traffic halved)
        float acc[64];
        #pragma unroll
        for (int i = 0; i < 64; ++i) acc[i] = 0.f;

        #pragma unroll 1
        for (int i = 0; i < 12; ++i) {
            const uint2* A = (i < 8) ? Ah2 : Al2;
            const int ks    = i & 3;
            const int bslot = (i < 8) ? i : (i - 8);
            const uint2 aA0 = A[ks * 512 + rA0 * 4 + jj];
            const uint2 aA1 = A[ks * 512 + (rA0 + 8) * 4 + jj];
            const uint2 aB0 = A[ks * 512 + rB0 * 4 + jj];
            const uint2 aB1 = A[ks * 512 + (rB0 + 8) * 4 + jj];
            const uint2* Bp = Bf2 + ((bslot * CC_TC + cbase + rl) * 4 + jj);
            #pragma unroll
            for (int t = 0; t < 8; ++t) {
                const uint2 b = Bp[t * 32];
                mma16816(acc + t * 8,     aA0.x, aA1.x, aA0.y, aA1.y, b.x, b.y);
                mma16816(acc + t * 8 + 4, aB0.x, aB1.x, aB0.y, aB1.y, b.x, b.y);
            }
        }

        // ---- epilogue: screening t = p2 - 2*mm (x2 dropped: row-constant,
        // argmin-equivalent; exact chain in rescue). Scores overwrite acc.
        float mnA0 = FLT_BIG, mnA1 = FLT_BIG, mnB0 = FLT_BIG, mnB1 = FLT_BIG;
        #pragma unroll
        for (int t = 0; t < 8; ++t) {
            const int c0 = cbase + t * 8 + 2 * jj;
            const float p0 = sP2[c0], p1 = sP2[c0 + 1];
            const float sA00 = __fmaf_rn(-2.f, acc[t*8+0], p0);
            const float sA01 = __fmaf_rn(-2.f, acc[t*8+1], p1);
            const float sA10 = __fmaf_rn(-2.f, acc[t*8+2], p0);
            const float sA11 = __fmaf_rn(-2.f, acc[t*8+3], p1);
            const float sB00 = __fmaf_rn(-2.f, acc[t*8+4], p0);
            const float sB01 = __fmaf_rn(-2.f, acc[t*8+5], p1);
            const float sB10 = __fmaf_rn(-2.f, acc[t*8+6], p0);
            const float sB11 = __fmaf_rn(-2.f, acc[t*8+7], p1);
            acc[t*8+0]=sA00; acc[t*8+1]=sA01; acc[t*8+2]=sA10; acc[t*8+3]=sA11;
            acc[t*8+4]=sB00; acc[t*8+5]=sB01; acc[t*8+6]=sB10; acc[t*8+7]=sB11;
            mnA0 = fminf(mnA0, fminf(sA00, sA01));
            mnA1 = fminf(mnA1, fminf(sA10, sA11));
            mnB0 = fminf(mnB0, fminf(sB00, sB01));
            mnB1 = fminf(mnB1, fminf(sB10, sB11));
        }
        mnA0 = fminf(mnA0, __shfl_xor_sync(0xFFFFFFFF, mnA0, 1));
        mnA0 = fminf(mnA0, __shfl_xor_sync(0xFFFFFFFF, mnA0, 2));
        mnA1 = fminf(mnA1, __shfl_xor_sync(0xFFFFFFFF, mnA1, 1));
        mnA1 = fminf(mnA1, __shfl_xor_sync(0xFFFFFFFF, mnA1, 2));
        mnB0 = fminf(mnB0, __shfl_xor_sync(0xFFFFFFFF, mnB0, 1));
        mnB0 = fminf(mnB0, __shfl_xor_sync(0xFFFFFFFF, mnB0, 2));
        mnB1 = fminf(mnB1, __shfl_xor_sync(0xFFFFFFFF, mnB1, 1));
        mnB1 = fminf(mnB1, __shfl_xor_sync(0xFFFFFFFF, mnB1, 2));
        if (jj == 0) {
            sPm[rA0 * 4 + q]       = mnA0;
            sPm[(rA0 + 8) * 4 + q] = mnA1;
            sPm[rB0 * 4 + q]       = mnB0;
            sPm[(rB0 + 8) * 4 + q] = mnB1;
        }
        __syncthreads();
        const float thrA0 = fminf(fminf(sPm[rA0*4], sPm[rA0*4+1]),
                                  fminf(sPm[rA0*4+2], sPm[rA0*4+3])) + MARGIN;
        const float thrA1 = fminf(fminf(sPm[(rA0+8)*4], sPm[(rA0+8)*4+1]),
                                  fminf(sPm[(rA0+8)*4+2], sPm[(rA0+8)*4+3])) + MARGIN;
        const float thrB0 = fminf(fminf(sPm[rB0*4], sPm[rB0*4+1]),
                                  fminf(sPm[rB0*4+2], sPm[rB0*4+3])) + MARGIN;
        const float thrB1 = fminf(fminf(sPm[(rB0+8)*4], sPm[(rB0+8)*4+1]),
                                  fminf(sPm[(rB0+8)*4+2], sPm[(rB0+8)*4+3])) + MARGIN;

        #pragma unroll
        for (int t = 0; t < 8; ++t) {
            const int c0 = cbase + t * 8 + 2 * jj;
            if (acc[t*8+0] < thrA0) { int p = atomicAdd(&sCn[rA0],   1); if (p < 8) sLs[rA0*8+p]     = c0;     }
            if (acc[t*8+1] < thrA0) { int p = atomicAdd(&sCn[rA0],   1); if (p < 8) sLs[rA0*8+p]     = c0 + 1; }
            if (acc[t*8+2] < thrA1) { int p = atomicAdd(&sCn[rA0+8], 1); if (p < 8) sLs[(rA0+8)*8+p] = c0;     }
            if (acc[t*8+3] < thrA1) { int p = atomicAdd(&sCn[rA0+8], 1); if (p < 8) sLs[(rA0+8)*8+p] = c0 + 1; }
            if (acc[t*8+4] < thrB0) { int p = atomicAdd(&sCn[rB0],   1); if (p < 8) sLs[rB0*8+p]     = c0;     }
            if (acc[t*8+5] < thrB0) { int p = atomicAdd(&sCn[rB0],   1); if (p < 8) sLs[rB0*8+p]     = c0 + 1; }
            if (acc[t*8+6] < thrB1) { int p = atomicAdd(&sCn[rB0+8], 1); if (p < 8) sLs[(rB0+8)*8+p] = c0;     }
            if (acc[t*8+7] < thrB1) { int p = atomicAdd(&sCn[rB0+8], 1); if (p < 8) sLs[(rB0+8)*8+p] = c0 + 1; }
        }
        __syncthreads();

        // resolve: q==0 && jj==0 threads own 4 rows each (exact R6 chain)
        if (q == 0 && jj == 0) {
            const int rows[4] = { rA0, rA0 + 8, rB0, rB0 + 8 };
            #pragma unroll 1
            for (int rr = 0; rr < 4; ++rr) {
                const int row = rows[rr];
                const int cnt = sCn[row];
                int pick;
                if (cnt == 1) {
                    pick = sLs[row * 8];     // provably the exact-chain argmin
                } else {
                    const float* xr = sXf + row * DD;
                    float x2 = 0.f;
                    #pragma unroll
                    for (int d = 0; d < DD; ++d)
                        x2 = __fadd_rn(x2, __fmul_rn(xr[d], xr[d]));
                    float bs = FLT_BIG; int bc = CC_TC; pick = 0;
                    if (cnt <= 8) {
                        for (int i = 0; i < cnt; ++i) {
                            const int c = sLs[row * 8 + i];
                            float mm = 0.f;
                            #pragma unroll
                            for (int d = 0; d < DD; ++d)
                                mm = __fmaf_rn(xr[d], __ldg(&Phi[c * DD + d]), mm);
                            const float s = __fsub_rn(__fadd_rn(x2, sP2[c]),
                                                      __fmul_rn(2.f, mm));
                            if (s < bs || (s == bs && c < bc)) { bs = s; bc = c; }
                        }
                        pick = bc;
                    } else {                 // truncated list: full exact scan
                        for (int c = 0; c < CC_TC; ++c) {
                            float mm = 0.f;
                            #pragma unroll
                            for (int d = 0; d < DD; ++d)
                                mm = __fmaf_rn(xr[d], __ldg(&Phi[c * DD + d]), mm);
                            const float s = __fsub_rn(__fadd_rn(x2, sP2[c]),
                                                      __fmul_rn(2.f, mm));
                            if (s < bs) { bs = s; pick = c; }
                        }
                    }
                }
                if (gbase + row < n) out[gbase + row] = (float)pick;
            }
        }
        buf ^= 1;
    }
}

// --------------------- R6 scalar fallback (D==50, any C) ---------------------
#define TPB   384
#define CHUNK 128
#define PPT   2
#define PTS_PER_BLOCK (TPB * PPT)

__global__ __launch_bounds__(TPB)
void kmeans_fast50(const float* __restrict__ X,
                   const float* __restrict__ Phi,
                   float* __restrict__ out, int n, int C)
{
    __shared__ __align__(16) float sPhiT[DD * CHUNK];
    __shared__ float sP2[CHUNK];

    const int base = blockIdx.x * PTS_PER_BLOCK;
    const int pt0  = base + threadIdx.x;
    const int pt1  = pt0 + TPB;

    float x0[DD], x1[DD];
    {
        const long long r0 = (long long)(pt0 < n ? pt0 : 0) * DD;
        const long long r1 = (long long)(pt1 < n ? pt1 : 0) * DD;
        const float2* a = reinterpret_cast<const float2*>(X + r0);
        const float2* b = reinterpret_cast<const float2*>(X + r1);
        #pragma unroll
        for (int j = 0; j < DD / 2; ++j) {
            float2 va = a[j]; x0[2*j] = va.x; x0[2*j+1] = va.y;
            float2 vb = b[j]; x1[2*j] = vb.x; x1[2*j+1] = vb.y;
        }
    }
    float x2a = 0.f, x2b = 0.f;
    #pragma unroll
    for (int d = 0; d < DD; ++d) {
        x2a = __fadd_rn(x2a, __fmul_rn(x0[d], x0[d]));
        x2b = __fadd_rn(x2b, __fmul_rn(x1[d], x1[d]));
    }

    float best0 = FLT_BIG, best1 = FLT_BIG;
    int   bi0 = 0, bi1 = 0;

    #pragma unroll 1
    for (int cb = 0; cb < C; cb += CHUNK) {
        const int cc = (C - cb < CHUNK) ? (C - cb) : CHUNK;
        __syncthreads();
        for (int i = threadIdx.x; i < cc * DD; i += TPB) {
            const int c = i / DD, d = i - c * DD;
            sPhiT[d * CHUNK + c] = Phi[(long long)(cb + c) * DD + d];
        }
        __syncthreads();
        if (threadIdx.x < cc) {
            float s = 0.f;
            #pragma unroll
            for (int d = 0; d < DD; ++d) {
                const float v = sPhiT[d * CHUNK + threadIdx.x];
                s = __fadd_rn(s, __fmul_rn(v, v));
            }
            sP2[threadIdx.x] = s;
        }
        __syncthreads();

        int c = 0;
        #pragma unroll 1
        for (; c + 4 <= cc; c += 4) {
            float a00=0.f,a01=0.f,a02=0.f,a03=0.f,a10=0.f,a11=0.f,a12=0.f,a13=0.f;
            const float4* pT = reinterpret_cast<const float4*>(sPhiT + c);
            #pragma unroll
            for (int d = 0; d < DD; ++d) {
                const float4 p = pT[d * (CHUNK / 4)];
                a00 = __fmaf_rn(x0[d], p.x, a00);
                a01 = __fmaf_rn(x0[d], p.y, a01);
                a02 = __fmaf_rn(x0[d], p.z, a02);
                a03 = __fmaf_rn(x0[d], p.w, a03);
                a10 = __fmaf_rn(x1[d], p.x, a10);
                a11 = __fmaf_rn(x1[d], p.y, a11);
                a12 = __fmaf_rn(x1[d], p.z, a12);
                a13 = __fmaf_rn(x1[d], p.w, a13);
            }
            const float q0=sP2[c],q1=sP2[c+1],q2=sP2[c+2],q3=sP2[c+3];
            const float s00=__fsub_rn(__fadd_rn(x2a,q0),__fmul_rn(2.f,a00));
            const float s01=__fsub_rn(__fadd_rn(x2a,q1),__fmul_rn(2.f,a01));
            const float s02=__fsub_rn(__fadd_rn(x2a,q2),__fmul_rn(2.f,a02));
            const float s03=__fsub_rn(__fadd_rn(x2a,q3),__fmul_rn(2.f,a03));
            const float s10=__fsub_rn(__fadd_rn(x2b,q0),__fmul_rn(2.f,a10));
            const float s11=__fsub_rn(__fadd_rn(x2b,q1),__fmul_rn(2.f,a11));
            const float s12=__fsub_rn(__fadd_rn(x2b,q2),__fmul_rn(2.f,a12));
            const float s13=__fsub_rn(__fadd_rn(x2b,q3),__fmul_rn(2.f,a13));
            const int g = cb + c;
            if (s00<best0){best0=s00;bi0=g;}   if (s01<best0){best0=s01;bi0=g+1;}
            if (s02<best0){best0=s02;bi0=g+2;} if (s03<best0){best0=s03;bi0=g+3;}
            if (s10<best1){best1=s10;bi1=g;}   if (s11<best1){best1=s11;bi1=g+1;}
            if (s12<best1){best1=s12;bi1=g+2;} if (s13<best1){best1=s13;bi1=g+3;}
        }
        for (; c < cc; ++c) {
            float a0=0.f,a1=0.f;
            #pragma unroll
            for (int d = 0; d < DD; ++d) {
                const float p = sPhiT[d * CHUNK + c];
                a0=__fmaf_rn(x0[d],p,a0); a1=__fmaf_rn(x1[d],p,a1);
            }
            const float q0 = sP2[c];
            const float s0=__fsub_rn(__fadd_rn(x2a,q0),__fmul_rn(2.f,a0));
            const float s1=__fsub_rn(__fadd_rn(x2b,q0),__fmul_rn(2.f,a1));
            if (s0<best0){best0=s0;bi0=cb+c;}
            if (s1<best1){best1=s1;bi1=cb+c;}
        }
    }
    if (pt0 < n) out[pt0] = (float)bi0;
    if (pt1 < n) out[pt1] = (float)bi1;
}

// --------------------- generic fallback: any D, C ---------------------
__global__ __launch_bounds__(256)
void kmeans_generic(const float* __restrict__ X,
                    const float* __restrict__ Phi,
                    float* __restrict__ out, int n, int D, int C)
{
    for (int idx = blockIdx.x * blockDim.x + threadIdx.x; idx < n;
         idx += gridDim.x * blockDim.x) {
        float xr[MAXD];
        const int Dc = (D < MAXD) ? D : MAXD;
        const long long row = (long long)idx * D;
        for (int d = 0; d < Dc; ++d) xr[d] = X[row + d];
        float x2 = 0.f;
        for (int d = 0; d < Dc; ++d) x2 = __fadd_rn(x2, __fmul_rn(xr[d], xr[d]));
        float best = FLT_BIG; int bi = 0;
        for (int c = 0; c < C; ++c) {
            const long long pr = (long long)c * D;
            float mm = 0.f, p2 = 0.f;
            for (int d = 0; d < Dc; ++d) {
                const float pv = __ldg(&Phi[pr + d]);
                mm = __fmaf_rn(xr[d], pv, mm);
                p2 = __fadd_rn(p2, __fmul_rn(pv, pv));
            }
            const float s = __fsub_rn(__fadd_rn(x2, p2), __fmul_rn(2.f, mm));
            if (s < best) { best = s; bi = c; }
        }
        out[idx] = (float)bi;
    }
}

// ------------------------------ launch ------------------------------
extern "C" void kernel_launch(void* const* d_in, const int* in_sizes, int n_in,
                              void* d_out, int out_size)
{
    int iX = 0;
    for (int i = 1; i < n_in; ++i)
        if (in_sizes[i] > in_sizes[iX]) iX = i;
    int iP = (iX == 0) ? (n_in > 1 ? 1 : 0) : 0;
    for (int i = 0; i < n_in; ++i)
        if (i != iX && in_sizes[i] > in_sizes[iP]) iP = i;

    const float* X   = (const float*)d_in[iX];
    const float* Phi = (const float*)d_in[iP];
    float*       out = (float*)d_out;

    const int n = out_size;
    if (n <= 0) return;
    const int D = in_sizes[iX] / n;
    const int C = (D > 0) ? in_sizes[iP] / D : 0;
    if (D <= 0 || C <= 0) return;

    if (D == DD && C == CC_TC) {
        prep_kernel<<<1, 256>>>(Phi);
        cudaFuncSetAttribute(kmeans_tc,
                             cudaFuncAttributeMaxDynamicSharedMemorySize, SM_TOT);
        const int ntiles = (n + TILE_M - 1) / TILE_M;
        const int grid = (ntiles < NSM) ? ntiles : NSM;
        kmeans_tc<<<grid, TPBT, SM_TOT>>>(X, Phi, out, n, ntiles);
    } else if (D == DD) {
        const int blocks = (n + PTS_PER_BLOCK - 1) / PTS_PER_BLOCK;
        kmeans_fast50<<<blocks, TPB>>>(X, Phi, out, n, C);
    } else {
        int blocks = (n + 255) / 256;
        if (blocks > 65535 * 8) blocks = 65535 * 8;
        kmeans_generic<<<blocks, 256>>>(X, Phi, out, n, D, C);
    }
}

// round 14
// speedup vs baseline: 1.0885x; 1.0044x over previous
#include <cuda_runtime.h>
#include <cuda_bf16.h>
#include <cstdint>

// kmeans assignment: persistent-CTA mma.sync bf16 3-term split + exact-chain
// rescue; output bit-identical to the R6 scalar chain (rel_err 9.9065e-4).
// R14: mma loop regrouped by k-step so each A fragment pair (hi+lo) and
// each B fragment pair loads ONCE and feeds all terms that use it:
// per ks: 8 A LDS + 16 B LDS + 48 mma  (LDS/warp/tile 144 -> 96, address
// ALU down proportionally). Accumulation order change is screening-only;
// resolved picks still come from the exact chain.

#define DD      50
#define CC_TC   256
#define TILE_M  128
#define MARGIN  0.02f
#define FLT_BIG 3.402823466e38f
#define MAXD    128
#define NSM     152
#define TPBT    512

typedef unsigned long long u64;

// smem byte offsets (dynamic)
#define SM_X0   0
#define SM_X1   (SM_X0 + TILE_M * DD * 4)            // 25600
#define SM_P2   (SM_X1 + TILE_M * DD * 4)            // 51200
#define SM_CNT  (SM_P2 + CC_TC * 4)                  // 52224
#define SM_LST  (SM_CNT + TILE_M * 4)                // 52736
#define SM_PMIN (SM_LST + TILE_M * 8 * 4)            // 56832
#define SM_AH   (SM_PMIN + TILE_M * 4 * 4)           // 58880
#define SM_AL   (SM_AH + 4 * TILE_M * 4 * 8)         // 75264
#define SM_BF   (SM_AL + 4 * TILE_M * 4 * 8)         // 91648
#define SM_TOT  (SM_BF + 8 * CC_TC * 4 * 8)          // 157184

// B fragments in mma order: gBfrag[slot<8][c<256][jj<4] = (b0,b1)
// slots 0..3 = Bh ks 0..3, slots 4..7 = Bl ks 0..3
__device__ __align__(16) u64 gBfrag[8 * CC_TC * 4];
__device__ float gP2[CC_TC];

__global__ void prep_kernel(const float* __restrict__ Phi)
{
    const int c = threadIdx.x;                 // 256 threads == 256 centroids
    unsigned short h[64], l[64];
    float s = 0.f;
    for (int d = 0; d < 64; ++d) {
        if (d < DD) {
            const float v  = Phi[c * DD + d];
            const __nv_bfloat16 bh = __float2bfloat16(v);
            const __nv_bfloat16 bl = __float2bfloat16(v - __bfloat162float(bh));
            h[d] = __bfloat16_as_ushort(bh);
            l[d] = __bfloat16_as_ushort(bl);
            s = __fadd_rn(s, __fmul_rn(v, v));  // exact R6 chain
        } else { h[d] = 0; l[d] = 0; }
    }
    gP2[c] = s;
    for (int ks = 0; ks < 4; ++ks)
        for (int jj = 0; jj < 4; ++jj) {
            const int k0 = 16 * ks + 2 * jj;        // b0 elements
            const int k1 = 16 * ks + 8 + 2 * jj;    // b1 elements
            const u64 vh = (u64)((uint32_t)h[k0] | ((uint32_t)h[k0+1] << 16))
                         | ((u64)((uint32_t)h[k1] | ((uint32_t)h[k1+1] << 16)) << 32);
            const u64 vl = (u64)((uint32_t)l[k0] | ((uint32_t)l[k0+1] << 16))
                         | ((u64)((uint32_t)l[k1] | ((uint32_t)l[k1+1] << 16)) << 32);
            gBfrag[(ks * CC_TC + c) * 4 + jj]       = vh;
            gBfrag[((4 + ks) * CC_TC + c) * 4 + jj] = vl;
        }
}

__device__ __forceinline__ uint32_t smem_u32(const void* p) {
    uint32_t a;
    asm("{ .reg .u64 t; cvta.to.shared.u64 t, %1; cvt.u32.u64 %0, t; }"
        : "=r"(a) : "l"(p));
    return a;
}
__device__ __forceinline__ void cp16(uint32_t saddr, const void* g) {
    asm volatile("cp.async.ca.shared.global [%0], [%1], 16;"
                 :: "r"(saddr), "l"(g));
}
__device__ __forceinline__ void mma16816(float* d, uint32_t a0, uint32_t a1,
                                         uint32_t a2, uint32_t a3,
                                         uint32_t b0, uint32_t b1) {
    asm volatile(
        "mma.sync.aligned.m16n8k16.row.col.f32.bf16.bf16.f32 "
        "{%0,%1,%2,%3}, {%4,%5,%6,%7}, {%8,%9}, {%0,%1,%2,%3};"
        : "+f"(d[0]), "+f"(d[1]), "+f"(d[2]), "+f"(d[3])
        : "r"(a0), "r"(a1), "r"(a2), "r"(a3), "r"(b0), "r"(b1));
}

__global__ __launch_bounds__(TPBT, 1)
void kmeans_tc(const float* __restrict__ X,
               const float* __restrict__ Phi,
               float* __restrict__ out, int n, int ntiles)
{
    extern __shared__ char smem[];
    const int tid  = threadIdx.x;
    const int w    = tid >> 5;
    const int lane = tid & 31;
    const int rl   = lane >> 2;
    const int jj   = lane & 3;
    const int q    = w & 3;              // centroid quarter (64 centroids)
    const int g    = w >> 2;             // row group (32 rows)
    const int cbase = q * 64;
    const int rA0 = g * 32 + rl;         // stripe0 rows: rA0, rA0+8
    const int rB0 = g * 32 + 16 + rl;    // stripe1 rows: rB0, rB0+8

    float*       sP2 = reinterpret_cast<float*>(smem + SM_P2);
    int*         sCn = reinterpret_cast<int*>(smem + SM_CNT);
    int*         sLs = reinterpret_cast<int*>(smem + SM_LST);
    float*       sPm = reinterpret_cast<float*>(smem + SM_PMIN); // [row][q]
    uint32_t*    AhW = reinterpret_cast<uint32_t*>(smem + SM_AH);
    uint32_t*    AlW = reinterpret_cast<uint32_t*>(smem + SM_AL);
    const uint2* Ah2 = reinterpret_cast<const uint2*>(smem + SM_AH);
    const uint2* Al2 = reinterpret_cast<const uint2*>(smem + SM_AL);
    const uint2* Bf2 = reinterpret_cast<const uint2*>(smem + SM_BF);
    u64*         Bf  = reinterpret_cast<u64*>(smem + SM_BF);

    const uint32_t sx0 = smem_u32(smem + SM_X0);
    const uint32_t sx1 = smem_u32(smem + SM_X1);

    int  tile = blockIdx.x;
    int  buf  = 0;
    bool pref = false;

    // prefetch first tile ASAP
    if (tile < ntiles) {
        const long long base = (long long)tile * TILE_M;
        if (base + TILE_M <= n) {
            const char* src = reinterpret_cast<const char*>(X + base * DD);
            for (int i = tid; i < TILE_M * DD * 4 / 16; i += TPBT)
                cp16(sx0 + i * 16, src + i * 16);
            pref = true;
        }
    }
    asm volatile("cp.async.commit_group;" ::: "memory");

    // one-time per CTA: copy B fragments + p2, zero A pad words (ks=3,q=1..7)
    {
        const u64* gb = gBfrag;
        for (int i = tid; i < 8 * CC_TC * 4; i += TPBT) Bf[i] = gb[i];
        for (int i = tid; i < CC_TC; i += TPBT) sP2[i] = gP2[i];
        for (int i = tid; i < TILE_M * 7 * 2; i += TPBT) {
            const int a = i / (TILE_M * 7);
            const int j = i - a * (TILE_M * 7);
            const int r = j / 7, qq = 1 + (j - r * 7);
            const int u = 3 * 1024 + r * 8 + (qq & 3) * 2 + (qq >> 2);
            (a ? AlW : AhW)[u] = 0u;
        }
    }

    for (; tile < ntiles; tile += gridDim.x) {
        const long long gbase = (long long)tile * TILE_M;
        const bool full = (gbase + TILE_M <= n);

        if (pref) asm volatile("cp.async.wait_group 0;" ::: "memory");
        __syncthreads();   // publish current X buffer; prev resolve done

        float* sXf = reinterpret_cast<float*>(smem + (buf ? SM_X1 : SM_X0));
        if (!full) {
            for (int idx = tid; idx < TILE_M * DD; idx += TPBT) {
                const int r = idx / DD, d = idx - r * DD;
                long long pt = gbase + r; if (pt >= n) pt = n - 1;
                sXf[idx] = X[pt * DD + d];
            }
            __syncthreads();
        }

        // owners zero candidate counters for their 4 rows
        if (q == 0 && jj == 0) {
            sCn[rA0] = 0; sCn[rA0 + 8] = 0;
            sCn[rB0] = 0; sCn[rB0 + 8] = 0;
        }

        // convert X -> bf16 hi/lo, fragment-ordered u32 slots
        for (int idx = tid; idx < TILE_M * 25; idx += TPBT) {
            const int r = idx / 25, p = idx - r * 25;
            const float2 v = *reinterpret_cast<const float2*>(sXf + r * DD + 2 * p);
            const __nv_bfloat16 h0 = __float2bfloat16(v.x);
            const __nv_bfloat16 h1 = __float2bfloat16(v.y);
            const __nv_bfloat16 l0 = __float2bfloat16(v.x - __bfloat162float(h0));
            const __nv_bfloat16 l1 = __float2bfloat16(v.y - __bfloat162float(h1));
            const int ks = p >> 3, qq = p & 7;
            const int u  = ks * 1024 + r * 8 + (qq & 3) * 2 + (qq >> 2);
            AhW[u] = (uint32_t)__bfloat16_as_ushort(h0)
                   | ((uint32_t)__bfloat16_as_ushort(h1) << 16);
            AlW[u] = (uint32_t)__bfloat16_as_ushort(l0)
                   | ((uint32_t)__bfloat16_as_ushort(l1) << 16);
        }
        __syncthreads();

        // prefetch next tile (overlaps mma + epilogue)
        {
            const int nt = tile + gridDim.x;
            pref = false;
            if (nt < ntiles) {
                const long long nb = (long long)nt * TILE_M;
                if (nb + TILE_M <= n) {
                    const char* src = reinterpret_cast<const char*>(X + nb * DD);
                    const uint32_t dst = buf ? sx0 : sx1;
                    for (int i = tid; i < TILE_M * DD * 4 / 16; i += TPBT)
                        cp16(dst + i * 16, src + i * 16);
                    pref = true;
                }
            }
            asm volatile("cp.async.commit_group;" ::: "memory");
        }

        // ---- mma regrouped by k-step: per ks load Ah+Al (8 LDS) once,
        // per t load bh+bl (2 LDS) once; issue all 6 dependent mma.
        float acc[64];
        #pragma unroll
        for (int i = 0; i < 64; ++i) acc[i] = 0.f;

        #pragma unroll 1
        for (int ks = 0; ks < 4; ++ks) {
            const uint2 hA0 = Ah2[ks * 512 + rA0 * 4 + jj];
            const uint2 hA1 = Ah2[ks * 512 + (rA0 + 8) * 4 + jj];
            const uint2 hB0 = Ah2[ks * 512 + rB0 * 4 + jj];
            const uint2 hB1 = Ah2[ks * 512 + (rB0 + 8) * 4 + jj];
            const uint2 lA0 = Al2[ks * 512 + rA0 * 4 + jj];
            const uint2 lA1 = Al2[ks * 512 + (rA0 + 8) * 4 + jj];
            const uint2 lB0 = Al2[ks * 512 + rB0 * 4 + jj];
            const uint2 lB1 = Al2[ks * 512 + (rB0 + 8) * 4 + jj];
            const uint2* Bph = Bf2 + ((ks * CC_TC + cbase + rl) * 4 + jj);
            const uint2* Bpl = Bf2 + (((4 + ks) * CC_TC + cbase + rl) * 4 + jj);
            #pragma unroll
            for (int t = 0; t < 8; ++t) {
                const uint2 bh = Bph[t * 32];
                const uint2 bl = Bpl[t * 32];
                float* a0 = acc + t * 8;
                float* a1 = acc + t * 8 + 4;
                mma16816(a0, hA0.x, hA1.x, hA0.y, hA1.y, bh.x, bh.y); // Ah.Bh s0
                mma16816(a1, hB0.x, hB1.x, hB0.y, hB1.y, bh.x, bh.y); // Ah.Bh s1
                mma16816(a0, hA0.x, hA1.x, hA0.y, hA1.y, bl.x, bl.y); // Ah.Bl s0
                mma16816(a1, hB0.x, hB1.x, hB0.y, hB1.y, bl.x, bl.y); // Ah.Bl s1
                mma16816(a0, lA0.x, lA1.x, lA0.y, lA1.y, bh.x, bh.y); // Al.Bh s0
                mma16816(a1, lB0.x, lB1.x, lB0.y, lB1.y, bh.x, bh.y); // Al.Bh s1
            }
        }

        // ---- epilogue: screening t = p2 - 2*mm (x2 dropped: row-constant,
        // argmin-equivalent; exact chain in rescue). Scores overwrite acc.
        float mnA0 = FLT_BIG, mnA1 = FLT_BIG, mnB0 = FLT_BIG, mnB1 = FLT_BIG;
        #pragma unroll
        for (int t = 0; t < 8; ++t) {
            const int c0 = cbase + t * 8 + 2 * jj;
            const float p0 = sP2[c0], p1 = sP2[c0 + 1];
            const float sA00 = __fmaf_rn(-2.f, acc[t*8+0], p0);
            const float sA01 = __fmaf_rn(-2.f, acc[t*8+1], p1);
            const float sA10 = __fmaf_rn(-2.f, acc[t*8+2], p0);
            const float sA11 = __fmaf_rn(-2.f, acc[t*8+3], p1);
            const float sB00 = __fmaf_rn(-2.f, acc[t*8+4], p0);
            const float sB01 = __fmaf_rn(-2.f, acc[t*8+5], p1);
            const float sB10 = __fmaf_rn(-2.f, acc[t*8+6], p0);
            const float sB11 = __fmaf_rn(-2.f, acc[t*8+7], p1);
            acc[t*8+0]=sA00; acc[t*8+1]=sA01; acc[t*8+2]=sA10; acc[t*8+3]=sA11;
            acc[t*8+4]=sB00; acc[t*8+5]=sB01; acc[t*8+6]=sB10; acc[t*8+7]=sB11;
            mnA0 = fminf(mnA0, fminf(sA00, sA01));
            mnA1 = fminf(mnA1, fminf(sA10, sA11));
            mnB0 = fminf(mnB0, fminf(sB00, sB01));
            mnB1 = fminf(mnB1, fminf(sB10, sB11));
        }
        mnA0 = fminf(mnA0, __shfl_xor_sync(0xFFFFFFFF, mnA0, 1));
        mnA0 = fminf(mnA0, __shfl_xor_sync(0xFFFFFFFF, mnA0, 2));
        mnA1 = fminf(mnA1, __shfl_xor_sync(0xFFFFFFFF, mnA1, 1));
        mnA1 = fminf(mnA1, __shfl_xor_sync(0xFFFFFFFF, mnA1, 2));
        mnB0 = fminf(mnB0, __shfl_xor_sync(0xFFFFFFFF, mnB0, 1));
        mnB0 = fminf(mnB0, __shfl_xor_sync(0xFFFFFFFF, mnB0, 2));
        mnB1 = fminf(mnB1, __shfl_xor_sync(0xFFFFFFFF, mnB1, 1));
        mnB1 = fminf(mnB1, __shfl_xor_sync(0xFFFFFFFF, mnB1, 2));
        if (jj == 0) {
            sPm[rA0 * 4 + q]       = mnA0;
            sPm[(rA0 + 8) * 4 + q] = mnA1;
            sPm[rB0 * 4 + q]       = mnB0;
            sPm[(rB0 + 8) * 4 + q] = mnB1;
        }
        __syncthreads();
        const float thrA0 = fminf(fminf(sPm[rA0*4], sPm[rA0*4+1]),
                                  fminf(sPm[rA0*4+2], sPm[rA0*4+3])) + MARGIN;
        const float thrA1 = fminf(fminf(sPm[(rA0+8)*4], sPm[(rA0+8)*4+1]),
                                  fminf(sPm[(rA0+8)*4+2], sPm[(rA0+8)*4+3])) + MARGIN;
        const float thrB0 = fminf(fminf(sPm[rB0*4], sPm[rB0*4+1]),
                                  fminf(sPm[rB0*4+2], sPm[rB0*4+3])) + MARGIN;
        const float thrB1 = fminf(fminf(sPm[(rB0+8)*4], sPm[(rB0+8)*4+1]),
                                  fminf(sPm[(rB0+8)*4+2], sPm[(rB0+8)*4+3])) + MARGIN;

        #pragma unroll
        for (int t = 0; t < 8; ++t) {
            const int c0 = cbase + t * 8 + 2 * jj;
            if (acc[t*8+0] < thrA0) { int p = atomicAdd(&sCn[rA0],   1); if (p < 8) sLs[rA0*8+p]     = c0;     }
            if (acc[t*8+1] < thrA0) { int p = atomicAdd(&sCn[rA0],   1); if (p < 8) sLs[rA0*8+p]     = c0 + 1; }
            if (acc[t*8+2] < thrA1) { int p = atomicAdd(&sCn[rA0+8], 1); if (p < 8) sLs[(rA0+8)*8+p] = c0;     }
            if (acc[t*8+3] < thrA1) { int p = atomicAdd(&sCn[rA0+8], 1); if (p < 8) sLs[(rA0+8)*8+p] = c0 + 1; }
            if (acc[t*8+4] < thrB0) { int p = atomicAdd(&sCn[rB0],   1); if (p < 8) sLs[rB0*8+p]     = c0;     }
            if (acc[t*8+5] < thrB0) { int p = atomicAdd(&sCn[rB0],   1); if (p < 8) sLs[rB0*8+p]     = c0 + 1; }
            if (acc[t*8+6] < thrB1) { int p = atomicAdd(&sCn[rB0+8], 1); if (p < 8) sLs[(rB0+8)*8+p] = c0;     }
            if (acc[t*8+7] < thrB1) { int p = atomicAdd(&sCn[rB0+8], 1); if (p < 8) sLs[(rB0+8)*8+p] = c0 + 1; }
        }
        __syncthreads();

        // resolve: q==0 && jj==0 threads own 4 rows each (exact R6 chain)
        if (q == 0 && jj == 0) {
            const int rows[4] = { rA0, rA0 + 8, rB0, rB0 + 8 };
            #pragma unroll 1
            for (int rr = 0; rr < 4; ++rr) {
                const int row = rows[rr];
                const int cnt = sCn[row];
                int pick;
                if (cnt == 1) {
                    pick = sLs[row * 8];     // provably the exact-chain argmin
                } else {
                    const float* xr = sXf + row * DD;
                    float x2 = 0.f;
                    #pragma unroll
                    for (int d = 0; d < DD; ++d)
                        x2 = __fadd_rn(x2, __fmul_rn(xr[d], xr[d]));
                    float bs = FLT_BIG; int bc = CC_TC; pick = 0;
                    if (cnt <= 8) {
                        for (int i = 0; i < cnt; ++i) {
                            const int c = sLs[row * 8 + i];
                            float mm = 0.f;
                            #pragma unroll
                            for (int d = 0; d < DD; ++d)
                                mm = __fmaf_rn(xr[d], __ldg(&Phi[c * DD + d]), mm);
                            const float s = __fsub_rn(__fadd_rn(x2, sP2[c]),
                                                      __fmul_rn(2.f, mm));
                            if (s < bs || (s == bs && c < bc)) { bs = s; bc = c; }
                        }
                        pick = bc;
                    } else {                 // truncated list: full exact scan
                        for (int c = 0; c < CC_TC; ++c) {
                            float mm = 0.f;
                            #pragma unroll
                            for (int d = 0; d < DD; ++d)
                                mm = __fmaf_rn(xr[d], __ldg(&Phi[c * DD + d]), mm);
                            const float s = __fsub_rn(__fadd_rn(x2, sP2[c]),
                                                      __fmul_rn(2.f, mm));
                            if (s < bs) { bs = s; pick = c; }
                        }
                    }
                }
                if (gbase + row < n) out[gbase + row] = (float)pick;
            }
        }
        buf ^= 1;
    }
}

// --------------------- R6 scalar fallback (D==50, any C) ---------------------
#define TPB   384
#define CHUNK 128
#define PPT   2
#define PTS_PER_BLOCK (TPB * PPT)

__global__ __launch_bounds__(TPB)
void kmeans_fast50(const float* __restrict__ X,
                   const float* __restrict__ Phi,
                   float* __restrict__ out, int n, int C)
{
    __shared__ __align__(16) float sPhiT[DD * CHUNK];
    __shared__ float sP2[CHUNK];

    const int base = blockIdx.x * PTS_PER_BLOCK;
    const int pt0  = base + threadIdx.x;
    const int pt1  = pt0 + TPB;

    float x0[DD], x1[DD];
    {
        const long long r0 = (long long)(pt0 < n ? pt0 : 0) * DD;
        const long long r1 = (long long)(pt1 < n ? pt1 : 0) * DD;
        const float2* a = reinterpret_cast<const float2*>(X + r0);
        const float2* b = reinterpret_cast<const float2*>(X + r1);
        #pragma unroll
        for (int j = 0; j < DD / 2; ++j) {
            float2 va = a[j]; x0[2*j] = va.x; x0[2*j+1] = va.y;
            float2 vb = b[j]; x1[2*j] = vb.x; x1[2*j+1] = vb.y;
        }
    }
    float x2a = 0.f, x2b = 0.f;
    #pragma unroll
    for (int d = 0; d < DD; ++d) {
        x2a = __fadd_rn(x2a, __fmul_rn(x0[d], x0[d]));
        x2b = __fadd_rn(x2b, __fmul_rn(x1[d], x1[d]));
    }

    float best0 = FLT_BIG, best1 = FLT_BIG;
    int   bi0 = 0, bi1 = 0;

    #pragma unroll 1
    for (int cb = 0; cb < C; cb += CHUNK) {
        const int cc = (C - cb < CHUNK) ? (C - cb) : CHUNK;
        __syncthreads();
        for (int i = threadIdx.x; i < cc * DD; i += TPB) {
            const int c = i / DD, d = i - c * DD;
            sPhiT[d * CHUNK + c] = Phi[(long long)(cb + c) * DD + d];
        }
        __syncthreads();
        if (threadIdx.x < cc) {
            float s = 0.f;
            #pragma unroll
            for (int d = 0; d < DD; ++d) {
                const float v = sPhiT[d * CHUNK + threadIdx.x];
                s = __fadd_rn(s, __fmul_rn(v, v));
            }
            sP2[threadIdx.x] = s;
        }
        __syncthreads();

        int c = 0;
        #pragma unroll 1
        for (; c + 4 <= cc; c += 4) {
            float a00=0.f,a01=0.f,a02=0.f,a03=0.f,a10=0.f,a11=0.f,a12=0.f,a13=0.f;
            const float4* pT = reinterpret_cast<const float4*>(sPhiT + c);
            #pragma unroll
            for (int d = 0; d < DD; ++d) {
                const float4 p = pT[d * (CHUNK / 4)];
                a00 = __fmaf_rn(x0[d], p.x, a00);
                a01 = __fmaf_rn(x0[d], p.y, a01);
                a02 = __fmaf_rn(x0[d], p.z, a02);
                a03 = __fmaf_rn(x0[d], p.w, a03);
                a10 = __fmaf_rn(x1[d], p.x, a10);
                a11 = __fmaf_rn(x1[d], p.y, a11);
                a12 = __fmaf_rn(x1[d], p.z, a12);
                a13 = __fmaf_rn(x1[d], p.w, a13);
            }
            const float q0=sP2[c],q1=sP2[c+1],q2=sP2[c+2],q3=sP2[c+3];
            const float s00=__fsub_rn(__fadd_rn(x2a,q0),__fmul_rn(2.f,a00));
            const float s01=__fsub_rn(__fadd_rn(x2a,q1),__fmul_rn(2.f,a01));
            const float s02=__fsub_rn(__fadd_rn(x2a,q2),__fmul_rn(2.f,a02));
            const float s03=__fsub_rn(__fadd_rn(x2a,q3),__fmul_rn(2.f,a03));
            const float s10=__fsub_rn(__fadd_rn(x2b,q0),__fmul_rn(2.f,a10));
            const float s11=__fsub_rn(__fadd_rn(x2b,q1),__fmul_rn(2.f,a11));
            const float s12=__fsub_rn(__fadd_rn(x2b,q2),__fmul_rn(2.f,a12));
            const float s13=__fsub_rn(__fadd_rn(x2b,q3),__fmul_rn(2.f,a13));
            const int gg = cb + c;
            if (s00<best0){best0=s00;bi0=gg;}   if (s01<best0){best0=s01;bi0=gg+1;}
            if (s02<best0){best0=s02;bi0=gg+2;} if (s03<best0){best0=s03;bi0=gg+3;}
            if (s10<best1){best1=s10;bi1=gg;}   if (s11<best1){best1=s11;bi1=gg+1;}
            if (s12<best1){best1=s12;bi1=gg+2;} if (s13<best1){best1=s13;bi1=gg+3;}
        }
        for (; c < cc; ++c) {
            float a0=0.f,a1=0.f;
            #pragma unroll
            for (int d = 0; d < DD; ++d) {
                const float p = sPhiT[d * CHUNK + c];
                a0=__fmaf_rn(x0[d],p,a0); a1=__fmaf_rn(x1[d],p,a1);
            }
            const float q0 = sP2[c];
            const float s0=__fsub_rn(__fadd_rn(x2a,q0),__fmul_rn(2.f,a0));
            const float s1=__fsub_rn(__fadd_rn(x2b,q0),__fmul_rn(2.f,a1));
            if (s0<best0){best0=s0;bi0=cb+c;}
            if (s1<best1){best1=s1;bi1=cb+c;}
        }
    }
    if (pt0 < n) out[pt0] = (float)bi0;
    if (pt1 < n) out[pt1] = (float)bi1;
}

// --------------------- generic fallback: any D, C ---------------------
__global__ __launch_bounds__(256)
void kmeans_generic(const float* __restrict__ X,
                    const float* __restrict__ Phi,
                    float* __restrict__ out, int n, int D, int C)
{
    for (int idx = blockIdx.x * blockDim.x + threadIdx.x; idx < n;
         idx += gridDim.x * blockDim.x) {
        float xr[MAXD];
        const int Dc = (D < MAXD) ? D : MAXD;
        const long long row = (long long)idx * D;
        for (int d = 0; d < Dc; ++d) xr[d] = X[row + d];
        float x2 = 0.f;
        for (int d = 0; d < Dc; ++d) x2 = __fadd_rn(x2, __fmul_rn(xr[d], xr[d]));
        float best = FLT_BIG; int bi = 0;
        for (int c = 0; c < C; ++c) {
            const long long pr = (long long)c * D;
            float mm = 0.f, p2 = 0.f;
            for (int d = 0; d < Dc; ++d) {
                const float pv = __ldg(&Phi[pr + d]);
                mm = __fmaf_rn(xr[d], pv, mm);
                p2 = __fadd_rn(p2, __fmul_rn(pv, pv));
            }
            const float s = __fsub_rn(__fadd_rn(x2, p2), __fmul_rn(2.f, mm));
            if (s < best) { best = s; bi = c; }
        }
        out[idx] = (float)bi;
    }
}

// ------------------------------ launch ------------------------------
extern "C" void kernel_launch(void* const* d_in, const int* in_sizes, int n_in,
                              void* d_out, int out_size)
{
    int iX = 0;
    for (int i = 1; i < n_in; ++i)
        if (in_sizes[i] > in_sizes[iX]) iX = i;
    int iP = (iX == 0) ? (n_in > 1 ? 1 : 0) : 0;
    for (int i = 0; i < n_in; ++i)
        if (i != iX && in_sizes[i] > in_sizes[iP]) iP = i;

    const float* X   = (const float*)d_in[iX];
    const float* Phi = (const float*)d_in[iP];
    float*       out = (float*)d_out;

    const int n = out_size;
    if (n <= 0) return;
    const int D = in_sizes[iX] / n;
    const int C = (D > 0) ? in_sizes[iP] / D : 0;
    if (D <= 0 || C <= 0) return;

    if (D == DD && C == CC_TC) {
        prep_kernel<<<1, 256>>>(Phi);
        cudaFuncSetAttribute(kmeans_tc,
                             cudaFuncAttributeMaxDynamicSharedMemorySize, SM_TOT);
        const int ntiles = (n + TILE_M - 1) / TILE_M;
        const int grid = (ntiles < NSM) ? ntiles : NSM;
        kmeans_tc<<<grid, TPBT, SM_TOT>>>(X, Phi, out, n, ntiles);
    } else if (D == DD) {
        const int blocks = (n + PTS_PER_BLOCK - 1) / PTS_PER_BLOCK;
        kmeans_fast50<<<blocks, TPB>>>(X, Phi, out, n, C);
    } else {
        int blocks = (n + 255) / 256;
        if (blocks > 65535 * 8) blocks = 65535 * 8;
        kmeans_generic<<<blocks, 256>>>(X, Phi, out, n, D, C);
    }
}